// round 4
// baseline (speedup 1.0000x reference)
#include <cuda_runtime.h>
#include <math.h>

#define T_SEQ  8192
#define HID    1024
#define GDIM   2048
#define NCTA   128
#define RECT   256          // 8 warps; warp w owns output cta*8+w (both matrix rows)
#define NCHUNK 16
#define CLEN   (T_SEQ / NCHUNK)   // 512

// ---------------- static scratch (no allocation) ----------------
__device__ float g_gi0[T_SEQ * GDIM];
__device__ float g_gi1[T_SEQ * GDIM];
__device__ float g_gi2[T_SEQ * GDIM];
__device__ float g_X0[T_SEQ * HID];
__device__ float g_X1[T_SEQ * HID];
__device__ float g_X2[T_SEQ * HID];
__device__ __align__(128) unsigned long long g_ht[3][2][HID];  // tagged h, per layer

__device__ __forceinline__ void st_tagged(unsigned long long* p, float v, unsigned tag) {
    unsigned long long pk = ((unsigned long long)tag << 32) |
                            (unsigned long long)__float_as_uint(v);
    asm volatile("st.global.relaxed.gpu.b64 [%0], %1;" :: "l"(p), "l"(pk) : "memory");
}

// ---------------- init: seed all 3 layers' tagged h ----------------
__global__ void init_all(const float* __restrict__ h0) {
    int i = threadIdx.x;   // 1024 threads
#pragma unroll
    for (int l = 0; l < 3; ++l) {
        g_ht[l][0][i] = (unsigned long long)__float_as_uint(h0[l * HID + i]); // tag 0
        g_ht[l][1][i] = 0xFFFFFFFF00000000ull;                                 // invalid
    }
}

// ---------------- C[M,N] = A[M,K] @ W[N,K]^T + bias[N] ----------------
__global__ __launch_bounds__(256, 2)
void gemm_bias_nt(const float* __restrict__ A, const float* __restrict__ W,
                  const float* __restrict__ bias, float* __restrict__ C,
                  int M, int N, int K) {
    __shared__ float As[8][128];
    __shared__ float Bs[8][128];
    const int tid  = threadIdx.x;
    const int bm   = blockIdx.y * 128;
    const int bn   = blockIdx.x * 128;
    const int lrow = tid >> 1;
    const int lcol = (tid & 1) << 2;
    const int ty   = tid >> 4;
    const int tx   = tid & 15;

    float acc[8][8];
#pragma unroll
    for (int i = 0; i < 8; ++i)
#pragma unroll
        for (int j = 0; j < 8; ++j) acc[i][j] = 0.f;

    const float* Aptr = A + (size_t)(bm + lrow) * K + lcol;
    const float* Wptr = W + (size_t)(bn + lrow) * K + lcol;

    for (int k0 = 0; k0 < K; k0 += 8) {
        float4 av = *(const float4*)(Aptr + k0);
        float4 wv = *(const float4*)(Wptr + k0);
        As[lcol + 0][lrow] = av.x; As[lcol + 1][lrow] = av.y;
        As[lcol + 2][lrow] = av.z; As[lcol + 3][lrow] = av.w;
        Bs[lcol + 0][lrow] = wv.x; Bs[lcol + 1][lrow] = wv.y;
        Bs[lcol + 2][lrow] = wv.z; Bs[lcol + 3][lrow] = wv.w;
        __syncthreads();
#pragma unroll
        for (int k = 0; k < 8; ++k) {
            float4 a0 = *(const float4*)&As[k][ty * 8];
            float4 a1 = *(const float4*)&As[k][ty * 8 + 4];
            float4 b0 = *(const float4*)&Bs[k][tx * 8];
            float4 b1 = *(const float4*)&Bs[k][tx * 8 + 4];
            float ar[8] = {a0.x, a0.y, a0.z, a0.w, a1.x, a1.y, a1.z, a1.w};
            float br[8] = {b0.x, b0.y, b0.z, b0.w, b1.x, b1.y, b1.z, b1.w};
#pragma unroll
            for (int i = 0; i < 8; ++i)
#pragma unroll
                for (int j = 0; j < 8; ++j) acc[i][j] += ar[i] * br[j];
        }
        __syncthreads();
    }

#pragma unroll
    for (int i = 0; i < 8; ++i) {
        int row = bm + ty * 8 + i;
#pragma unroll
        for (int j = 0; j < 8; j += 4) {
            float4 v;
            int col = bn + tx * 8 + j;
            v.x = acc[i][j + 0] + bias[col + 0];
            v.y = acc[i][j + 1] + bias[col + 1];
            v.z = acc[i][j + 2] + bias[col + 2];
            v.w = acc[i][j + 3] + bias[col + 3];
            *(float4*)&C[(size_t)row * N + col] = v;
        }
    }
}

// ---------------- MGU recurrence for one layer, timestep range [t0,t1) ----------------
// 128 CTAs x 256 threads. Warp w computes output out=cta*8+w: rows out and HID+out.
__global__ __launch_bounds__(RECT, 2)
void mgu_recur(const float* __restrict__ w_hh, const float* __restrict__ b_hh,
               const float* __restrict__ gi, float* __restrict__ X,
               unsigned long long* __restrict__ ht, int t0, int t1) {
    __shared__ __align__(16) float h_s[2][HID];

    const int cta  = blockIdx.x;
    const int tid  = threadIdx.x;
    const int warp = tid >> 5;
    const int lane = tid & 31;
    const int out  = cta * 8 + warp;

    float4 wf[8], wn[8];
#pragma unroll
    for (int i = 0; i < 8; ++i) {
        int col = 4 * (i * 32 + lane);
        wf[i] = *(const float4*)&w_hh[(size_t)out * HID + col];
        wn[i] = *(const float4*)&w_hh[(size_t)(HID + out) * HID + col];
    }
    const float bf  = b_hh[out];
    const float bn2 = b_hh[HID + out];

    for (int t = t0; t < t1; ++t) {
        const int p = t & 1;

        // gi prefetch, independent of the poll
        float gif = 0.f, gin = 0.f;
        if (lane == 0) {
            gif = __ldcg(&gi[(size_t)t * GDIM + out]);
            gin = __ldcg(&gi[(size_t)t * GDIM + HID + out]);
        }

        // poll own 4 tagged words (value lo32, tag hi32) until fresh
        const unsigned long long* src = ht + (size_t)p * HID + 4 * tid;
        unsigned a0, a1, a2, a3, b0, b1, b2, b3;
        const unsigned tt = (unsigned)t;
        for (;;) {
            asm volatile("ld.volatile.global.v4.b32 {%0,%1,%2,%3}, [%4];"
                         : "=r"(a0), "=r"(a1), "=r"(a2), "=r"(a3) : "l"(src));
            asm volatile("ld.volatile.global.v4.b32 {%0,%1,%2,%3}, [%4];"
                         : "=r"(b0), "=r"(b1), "=r"(b2), "=r"(b3) : "l"(src + 2));
            if (a1 == tt && a3 == tt && b1 == tt && b3 == tt) break;
        }
        float* dst = &h_s[p][4 * tid];
        dst[0] = __uint_as_float(a0); dst[1] = __uint_as_float(a2);
        dst[2] = __uint_as_float(b0); dst[3] = __uint_as_float(b2);
        __syncthreads();

        // two 1024-length dots (forget + candidate rows), weights in registers
        float af0 = 0.f, af1 = 0.f, an0 = 0.f, an1 = 0.f;
#pragma unroll
        for (int i = 0; i < 8; i += 2) {
            float4 ha = *(const float4*)&h_s[p][4 * (i * 32 + lane)];
            float4 hb = *(const float4*)&h_s[p][4 * ((i + 1) * 32 + lane)];
            af0 += wf[i].x * ha.x + wf[i].y * ha.y + wf[i].z * ha.z + wf[i].w * ha.w;
            an0 += wn[i].x * ha.x + wn[i].y * ha.y + wn[i].z * ha.z + wn[i].w * ha.w;
            af1 += wf[i+1].x * hb.x + wf[i+1].y * hb.y + wf[i+1].z * hb.z + wf[i+1].w * hb.w;
            an1 += wn[i+1].x * hb.x + wn[i+1].y * hb.y + wn[i+1].z * hb.z + wn[i+1].w * hb.w;
        }
        float accf = af0 + af1;
        float accn = an0 + an1;
#pragma unroll
        for (int off = 16; off; off >>= 1) {
            accf += __shfl_down_sync(0xffffffffu, accf, off);
            accn += __shfl_down_sync(0xffffffffu, accn, off);
        }

        if (lane == 0) {
            float zf = gif + accf + bf;
            zf = fminf(fmaxf(zf, -30.f), 30.f);
            float f  = __fdividef(1.f, 1.f + __expf(-zf));
            float z  = gin + f * (accn + bn2);
            z = fminf(fmaxf(z, -15.f), 15.f);
            float e  = __expf(2.f * z);
            float n  = 1.f - __fdividef(2.f, e + 1.f);
            float hprev = h_s[p][out];
            float hy = n + (1.f - f) * (hprev - n);
            st_tagged(&ht[(size_t)(p ^ 1) * HID + out], hy, (unsigned)(t + 1));
            X[(size_t)t * HID + out] = hy;
        }
        // no trailing sync: h_s double-buffered; next step's __syncthreads gates reuse
    }
}

// ---------------- final projection ----------------
__global__ void out_proj(const float* __restrict__ X, const float* __restrict__ w_out,
                         const float* __restrict__ b_out, float* __restrict__ out) {
    int gwarp = (blockIdx.x * blockDim.x + threadIdx.x) >> 5;
    int lane  = threadIdx.x & 31;
    if (gwarp >= T_SEQ) return;
    float acc = 0.f;
#pragma unroll
    for (int i = 0; i < HID / 32; ++i)
        acc += X[(size_t)gwarp * HID + i * 32 + lane] * w_out[i * 32 + lane];
#pragma unroll
    for (int off = 16; off; off >>= 1) acc += __shfl_down_sync(0xffffffffu, acc, off);
    if (lane == 0) out[gwarp] = acc + b_out[0];
}

// ---------------- host launcher: chunked wavefront pipeline over streams ----------------
extern "C" void kernel_launch(void* const* d_in, const int* in_sizes, int n_in,
                              void* d_out, int out_size) {
    const float* S         = (const float*)d_in[0];
    const float* h0        = (const float*)d_in[1];
    const float* w_ih0     = (const float*)d_in[2];
    const float* w_hh0     = (const float*)d_in[3];
    const float* b_ih0     = (const float*)d_in[4];
    const float* b_hh0     = (const float*)d_in[5];
    const float* w_ih_rest = (const float*)d_in[6];
    const float* w_hh_rest = (const float*)d_in[7];
    const float* b_ih_rest = (const float*)d_in[8];
    const float* b_hh_rest = (const float*)d_in[9];
    const float* w_out     = (const float*)d_in[10];
    const float* b_out     = (const float*)d_in[11];
    float* out             = (float*)d_out;

    float *gi0, *gi1, *gi2, *X0, *X1, *X2;
    unsigned long long* ht;
    cudaGetSymbolAddress((void**)&gi0, g_gi0);
    cudaGetSymbolAddress((void**)&gi1, g_gi1);
    cudaGetSymbolAddress((void**)&gi2, g_gi2);
    cudaGetSymbolAddress((void**)&X0, g_X0);
    cudaGetSymbolAddress((void**)&X1, g_X1);
    cudaGetSymbolAddress((void**)&X2, g_X2);
    cudaGetSymbolAddress((void**)&ht, g_ht);
    unsigned long long* ht0 = ht;
    unsigned long long* ht1 = ht + 2 * HID;
    unsigned long long* ht2 = ht + 4 * HID;

    const float* w_hh1 = w_hh_rest;
    const float* w_hh2 = w_hh_rest + (size_t)GDIM * HID;
    const float* b_hh1 = b_hh_rest;
    const float* b_hh2 = b_hh_rest + GDIM;
    const float* w_ih1 = w_ih_rest;
    const float* w_ih2 = w_ih_rest + (size_t)GDIM * HID;
    const float* b_ih1 = b_ih_rest;
    const float* b_ih2 = b_ih_rest + GDIM;

    // side streams + events (created per call; destroyed at end)
    cudaStream_t sG1, sR1, sG2, sR2;
    cudaStreamCreateWithFlags(&sG1, cudaStreamNonBlocking);
    cudaStreamCreateWithFlags(&sR1, cudaStreamNonBlocking);
    cudaStreamCreateWithFlags(&sG2, cudaStreamNonBlocking);
    cudaStreamCreateWithFlags(&sR2, cudaStreamNonBlocking);

    cudaEvent_t evR0[NCHUNK], evG1[NCHUNK], evR1[NCHUNK], evG2[NCHUNK], evR2[NCHUNK];
    for (int c = 0; c < NCHUNK; ++c) {
        cudaEventCreateWithFlags(&evR0[c], cudaEventDisableTiming);
        cudaEventCreateWithFlags(&evG1[c], cudaEventDisableTiming);
        cudaEventCreateWithFlags(&evR1[c], cudaEventDisableTiming);
        cudaEventCreateWithFlags(&evG2[c], cudaEventDisableTiming);
        cudaEventCreateWithFlags(&evR2[c], cudaEventDisableTiming);
    }

    dim3 gchunk(GDIM / 128, CLEN / 128);   // (16, 4)

    // prologue on origin stream: init tags + full layer-0 input projection
    init_all<<<1, 1024>>>(h0);
    gemm_bias_nt<<<dim3(GDIM / 128, T_SEQ / 128), 256>>>(S, w_ih0, b_ih0, gi0,
                                                         T_SEQ, GDIM, 128);

    for (int c = 0; c < NCHUNK; ++c) {
        int t0 = c * CLEN, t1 = t0 + CLEN;

        // R0(c) on origin stream (throttled: don't run >2 chunks ahead of R1)
        if (c >= 2) cudaStreamWaitEvent(0, evR1[c - 2], 0);
        mgu_recur<<<NCTA, RECT>>>(w_hh0, b_hh0, gi0, X0, ht0, t0, t1);
        cudaEventRecord(evR0[c], 0);

        // G1(c): gi1 chunk from X0 chunk
        cudaStreamWaitEvent(sG1, evR0[c], 0);
        gemm_bias_nt<<<gchunk, 256, 0, sG1>>>(X0 + (size_t)t0 * HID, w_ih1, b_ih1,
                                              gi1 + (size_t)t0 * GDIM, CLEN, GDIM, HID);
        cudaEventRecord(evG1[c], sG1);

        // R1(c) (throttled vs R2)
        cudaStreamWaitEvent(sR1, evG1[c], 0);
        if (c >= 2) cudaStreamWaitEvent(sR1, evR2[c - 2], 0);
        mgu_recur<<<NCTA, RECT, 0, sR1>>>(w_hh1, b_hh1, gi1, X1, ht1, t0, t1);
        cudaEventRecord(evR1[c], sR1);

        // G2(c)
        cudaStreamWaitEvent(sG2, evR1[c], 0);
        gemm_bias_nt<<<gchunk, 256, 0, sG2>>>(X1 + (size_t)t0 * HID, w_ih2, b_ih2,
                                              gi2 + (size_t)t0 * GDIM, CLEN, GDIM, HID);
        cudaEventRecord(evG2[c], sG2);

        // R2(c)
        cudaStreamWaitEvent(sR2, evG2[c], 0);
        mgu_recur<<<NCTA, RECT, 0, sR2>>>(w_hh2, b_hh2, gi2, X2, ht2, t0, t1);
        cudaEventRecord(evR2[c], sR2);
    }

    // join back to origin and run final projection
    cudaStreamWaitEvent(0, evR2[NCHUNK - 1], 0);
    out_proj<<<T_SEQ * 32 / 256, 256>>>(X2, w_out, b_out, out);

    for (int c = 0; c < NCHUNK; ++c) {
        cudaEventDestroy(evR0[c]); cudaEventDestroy(evG1[c]); cudaEventDestroy(evR1[c]);
        cudaEventDestroy(evG2[c]); cudaEventDestroy(evR2[c]);
    }
    cudaStreamDestroy(sG1); cudaStreamDestroy(sR1);
    cudaStreamDestroy(sG2); cudaStreamDestroy(sR2);
}

// round 5
// speedup vs baseline: 1.3817x; 1.3817x over previous
#include <cuda_runtime.h>
#include <math.h>

#define T_SEQ 8192
#define HID   1024
#define GDIM  2048
#define NCTA  128
#define RECT  256            // 8 warps; warp w owns output cta*8+w (both rows)

// Tagged hidden state, slice-spread: 4 tagged words (32 B) per 256 B granule.
// One buffer = 256 granules = 64 KB -> engages ~all 184 LTS slices
// (bit 7 transparent in the addr->LTS hash, so 256 B is the spread quantum).
#define GRP_WORDS 32                       // 8B words per 256B granule
#define BUF_WORDS (256 * GRP_WORDS)        // 8192 words = 64 KB per buffer

// ---------------- static scratch (no allocation) ----------------
__device__ float g_gi[T_SEQ * GDIM];       // input projection (reused per layer)
__device__ float g_Xa[T_SEQ * HID];
__device__ float g_Xb[T_SEQ * HID];
__device__ __align__(256) unsigned long long g_ht[3][2 * BUF_WORDS];  // per-layer spread h

__device__ __forceinline__ size_t ht_idx(int word) {     // word in [0,1024)
    return (size_t)(word >> 2) * GRP_WORDS + (word & 3);
}
__device__ __forceinline__ void st_tagged(unsigned long long* p, float v, unsigned tag) {
    unsigned long long pk = ((unsigned long long)tag << 32) |
                            (unsigned long long)__float_as_uint(v);
    asm volatile("st.global.relaxed.gpu.b64 [%0], %1;" :: "l"(p), "l"(pk) : "memory");
}

// ---------------- init: seed all 3 layers' tagged h ----------------
__global__ void init_all(const float* __restrict__ h0) {
    int i = threadIdx.x;   // 1024 threads, word i
#pragma unroll
    for (int l = 0; l < 3; ++l) {
        g_ht[l][ht_idx(i)] = (unsigned long long)__float_as_uint(h0[l * HID + i]);
        g_ht[l][BUF_WORDS + ht_idx(i)] = 0xFFFFFFFF00000000ull;   // invalid tag
    }
}

// ---------------- C[M,N] = A[M,K] @ W[N,K]^T + bias[N] ----------------
__global__ __launch_bounds__(256, 2)
void gemm_bias_nt(const float* __restrict__ A, const float* __restrict__ W,
                  const float* __restrict__ bias, float* __restrict__ C,
                  int M, int N, int K) {
    __shared__ float As[8][128];
    __shared__ float Bs[8][128];
    const int tid  = threadIdx.x;
    const int bm   = blockIdx.y * 128;
    const int bn   = blockIdx.x * 128;
    const int lrow = tid >> 1;
    const int lcol = (tid & 1) << 2;
    const int ty   = tid >> 4;
    const int tx   = tid & 15;

    float acc[8][8];
#pragma unroll
    for (int i = 0; i < 8; ++i)
#pragma unroll
        for (int j = 0; j < 8; ++j) acc[i][j] = 0.f;

    const float* Aptr = A + (size_t)(bm + lrow) * K + lcol;
    const float* Wptr = W + (size_t)(bn + lrow) * K + lcol;

    for (int k0 = 0; k0 < K; k0 += 8) {
        float4 av = *(const float4*)(Aptr + k0);
        float4 wv = *(const float4*)(Wptr + k0);
        As[lcol + 0][lrow] = av.x; As[lcol + 1][lrow] = av.y;
        As[lcol + 2][lrow] = av.z; As[lcol + 3][lrow] = av.w;
        Bs[lcol + 0][lrow] = wv.x; Bs[lcol + 1][lrow] = wv.y;
        Bs[lcol + 2][lrow] = wv.z; Bs[lcol + 3][lrow] = wv.w;
        __syncthreads();
#pragma unroll
        for (int k = 0; k < 8; ++k) {
            float4 a0 = *(const float4*)&As[k][ty * 8];
            float4 a1 = *(const float4*)&As[k][ty * 8 + 4];
            float4 b0 = *(const float4*)&Bs[k][tx * 8];
            float4 b1 = *(const float4*)&Bs[k][tx * 8 + 4];
            float ar[8] = {a0.x, a0.y, a0.z, a0.w, a1.x, a1.y, a1.z, a1.w};
            float br[8] = {b0.x, b0.y, b0.z, b0.w, b1.x, b1.y, b1.z, b1.w};
#pragma unroll
            for (int i = 0; i < 8; ++i)
#pragma unroll
                for (int j = 0; j < 8; ++j) acc[i][j] += ar[i] * br[j];
        }
        __syncthreads();
    }

#pragma unroll
    for (int i = 0; i < 8; ++i) {
        int row = bm + ty * 8 + i;
#pragma unroll
        for (int j = 0; j < 8; j += 4) {
            float4 v;
            int col = bn + tx * 8 + j;
            v.x = acc[i][j + 0] + bias[col + 0];
            v.y = acc[i][j + 1] + bias[col + 1];
            v.z = acc[i][j + 2] + bias[col + 2];
            v.w = acc[i][j + 3] + bias[col + 3];
            *(float4*)&C[(size_t)row * N + col] = v;
        }
    }
}

// ---------------- persistent MGU recurrence, slice-spread flag-in-data ----------------
// 128 CTAs x 256 threads. Warp w: output out=cta*8+w, matrix rows out and HID+out.
// Thread tid polls/stages h words 4*tid..4*tid+3 (== granule tid).
__global__ __launch_bounds__(RECT, 2)
void mgu_recur(const float* __restrict__ w_hh, const float* __restrict__ b_hh,
               const float* __restrict__ gi, float* __restrict__ X,
               unsigned long long* __restrict__ ht) {
    __shared__ __align__(16) float h_s[2][HID];

    const int cta  = blockIdx.x;
    const int tid  = threadIdx.x;
    const int warp = tid >> 5;
    const int lane = tid & 31;
    const int out  = cta * 8 + warp;

    float4 wf[8], wn[8];
#pragma unroll
    for (int i = 0; i < 8; ++i) {
        int col = 4 * (i * 32 + lane);
        wf[i] = *(const float4*)&w_hh[(size_t)out * HID + col];
        wn[i] = *(const float4*)&w_hh[(size_t)(HID + out) * HID + col];
    }
    const float bf  = b_hh[out];
    const float bn2 = b_hh[HID + out];

    // this thread's granule (poll source) and this warp's publish slot
    unsigned long long* const grp0 = ht + (size_t)tid * GRP_WORDS;          // buffer 0
    unsigned long long* const pub0 = ht + ht_idx(out);                      // buffer 0
    const size_t boff = BUF_WORDS;

    for (int t = 0; t < T_SEQ; ++t) {
        const int p = t & 1;

        // gi prefetch (independent of the poll)
        float gif = 0.f, gin = 0.f;
        if (lane == 0) {
            gif = __ldcg(&gi[(size_t)t * GDIM + out]);
            gin = __ldcg(&gi[(size_t)t * GDIM + HID + out]);
        }

        // poll own granule (4 tagged words: value lo32, tag hi32) until fresh
        const unsigned long long* src = grp0 + (p ? boff : 0);
        unsigned a0, a1, a2, a3, b0, b1, b2, b3;
        const unsigned tt = (unsigned)t;
        for (;;) {
            asm volatile("ld.volatile.global.v4.b32 {%0,%1,%2,%3}, [%4];"
                         : "=r"(a0), "=r"(a1), "=r"(a2), "=r"(a3) : "l"(src));
            asm volatile("ld.volatile.global.v4.b32 {%0,%1,%2,%3}, [%4];"
                         : "=r"(b0), "=r"(b1), "=r"(b2), "=r"(b3) : "l"(src + 2));
            if (a1 == tt && a3 == tt && b1 == tt && b3 == tt) break;
        }
        float* dst = &h_s[p][4 * tid];
        dst[0] = __uint_as_float(a0); dst[1] = __uint_as_float(a2);
        dst[2] = __uint_as_float(b0); dst[3] = __uint_as_float(b2);
        __syncthreads();

        // two 1024-length dots (forget + candidate), weights in registers
        float af0 = 0.f, af1 = 0.f, an0 = 0.f, an1 = 0.f;
#pragma unroll
        for (int i = 0; i < 8; i += 2) {
            float4 ha = *(const float4*)&h_s[p][4 * (i * 32 + lane)];
            float4 hb = *(const float4*)&h_s[p][4 * ((i + 1) * 32 + lane)];
            af0 += wf[i].x * ha.x + wf[i].y * ha.y + wf[i].z * ha.z + wf[i].w * ha.w;
            an0 += wn[i].x * ha.x + wn[i].y * ha.y + wn[i].z * ha.z + wn[i].w * ha.w;
            af1 += wf[i+1].x * hb.x + wf[i+1].y * hb.y + wf[i+1].z * hb.z + wf[i+1].w * hb.w;
            an1 += wn[i+1].x * hb.x + wn[i+1].y * hb.y + wn[i+1].z * hb.z + wn[i+1].w * hb.w;
        }
        float accf = af0 + af1;
        float accn = an0 + an1;
#pragma unroll
        for (int off = 16; off; off >>= 1) {
            accf += __shfl_down_sync(0xffffffffu, accf, off);
            accn += __shfl_down_sync(0xffffffffu, accn, off);
        }

        if (lane == 0) {
            float zf = gif + accf + bf;
            zf = fminf(fmaxf(zf, -30.f), 30.f);
            float f  = __fdividef(1.f, 1.f + __expf(-zf));
            float z  = gin + f * (accn + bn2);
            z = fminf(fmaxf(z, -15.f), 15.f);
            float e  = __expf(2.f * z);
            float n  = 1.f - __fdividef(2.f, e + 1.f);
            float hprev = h_s[p][out];
            float hy = n + (1.f - f) * (hprev - n);
            st_tagged(pub0 + ((p ^ 1) ? boff : 0), hy, (unsigned)(t + 1));
            X[(size_t)t * HID + out] = hy;
        }
        // h_s double-buffered; next step's __syncthreads gates reuse
    }
}

// ---------------- final projection ----------------
__global__ void out_proj(const float* __restrict__ X, const float* __restrict__ w_out,
                         const float* __restrict__ b_out, float* __restrict__ out) {
    int gwarp = (blockIdx.x * blockDim.x + threadIdx.x) >> 5;
    int lane  = threadIdx.x & 31;
    if (gwarp >= T_SEQ) return;
    float acc = 0.f;
#pragma unroll
    for (int i = 0; i < HID / 32; ++i)
        acc += X[(size_t)gwarp * HID + i * 32 + lane] * w_out[i * 32 + lane];
#pragma unroll
    for (int off = 16; off; off >>= 1) acc += __shfl_down_sync(0xffffffffu, acc, off);
    if (lane == 0) out[gwarp] = acc + b_out[0];
}

// ---------------- host launcher (serial, known-good structure) ----------------
extern "C" void kernel_launch(void* const* d_in, const int* in_sizes, int n_in,
                              void* d_out, int out_size) {
    const float* S         = (const float*)d_in[0];
    const float* h0        = (const float*)d_in[1];
    const float* w_ih0     = (const float*)d_in[2];
    const float* w_hh0     = (const float*)d_in[3];
    const float* b_ih0     = (const float*)d_in[4];
    const float* b_hh0     = (const float*)d_in[5];
    const float* w_ih_rest = (const float*)d_in[6];
    const float* w_hh_rest = (const float*)d_in[7];
    const float* b_ih_rest = (const float*)d_in[8];
    const float* b_hh_rest = (const float*)d_in[9];
    const float* w_out     = (const float*)d_in[10];
    const float* b_out     = (const float*)d_in[11];
    float* out             = (float*)d_out;

    float *gi, *Xa, *Xb;
    unsigned long long* ht;
    cudaGetSymbolAddress((void**)&gi, g_gi);
    cudaGetSymbolAddress((void**)&Xa, g_Xa);
    cudaGetSymbolAddress((void**)&Xb, g_Xb);
    cudaGetSymbolAddress((void**)&ht, g_ht);

    dim3 ggrid(GDIM / 128, T_SEQ / 128);

    init_all<<<1, 1024>>>(h0);

    // ---- layer 0 ----
    gemm_bias_nt<<<ggrid, 256>>>(S, w_ih0, b_ih0, gi, T_SEQ, GDIM, 128);
    mgu_recur<<<NCTA, RECT>>>(w_hh0, b_hh0, gi, Xa, ht);

    // ---- layer 1 ----
    gemm_bias_nt<<<ggrid, 256>>>(Xa, w_ih_rest, b_ih_rest, gi, T_SEQ, GDIM, HID);
    mgu_recur<<<NCTA, RECT>>>(w_hh_rest, b_hh_rest, gi, Xb, ht + 2 * BUF_WORDS);

    // ---- layer 2 ----
    gemm_bias_nt<<<ggrid, 256>>>(Xb, w_ih_rest + (size_t)GDIM * HID,
                                 b_ih_rest + GDIM, gi, T_SEQ, GDIM, HID);
    mgu_recur<<<NCTA, RECT>>>(w_hh_rest + (size_t)GDIM * HID,
                              b_hh_rest + GDIM, gi, Xa, ht + 4 * BUF_WORDS);

    // ---- output projection ----
    out_proj<<<T_SEQ * 32 / 256, 256>>>(Xa, w_out, b_out, out);
}

// round 6
// speedup vs baseline: 1.5024x; 1.0873x over previous
#include <cuda_runtime.h>
#include <math.h>

#define T_SEQ 8192
#define HID   1024
#define GDIM  2048
#define NCTA  128
#define RECT  256            // 8 warps; warp w owns output cta*8+w for all 3 layers

// tagged hidden state, slice-spread: 4 tagged 8B words per 256B granule
#define GRPW 32                         // 8B words per 256B granule
#define BUFW (256 * GRPW)               // one buffer = 64 KB

// ---------------- static scratch (no allocation) ----------------
__device__ float g_gi[T_SEQ * GDIM];    // layer-0 input projection
__device__ float g_X2[T_SEQ * HID];     // layer-2 outputs
__device__ __align__(256) unsigned long long g_ht[3][2 * BUFW];

__device__ __forceinline__ size_t ht_idx(int word) {
    return (size_t)(word >> 2) * GRPW + (word & 3);
}
__device__ __forceinline__ void st_tagged(unsigned long long* p, float v, unsigned tag) {
    unsigned long long pk = ((unsigned long long)tag << 32) |
                            (unsigned long long)__float_as_uint(v);
    asm volatile("st.global.relaxed.gpu.b64 [%0], %1;" :: "l"(p), "l"(pk) : "memory");
}
#define LDV4(d0,d1,d2,d3,ptr) \
    asm volatile("ld.volatile.global.v4.b32 {%0,%1,%2,%3}, [%4];" \
                 : "=r"(d0),"=r"(d1),"=r"(d2),"=r"(d3) : "l"(ptr))

// ---------------- init: seed all 3 layers' tagged h ----------------
__global__ void init_all(const float* __restrict__ h0) {
    int i = threadIdx.x;   // 1024 threads
#pragma unroll
    for (int l = 0; l < 3; ++l) {
        g_ht[l][ht_idx(i)] = (unsigned long long)__float_as_uint(h0[l * HID + i]);
        g_ht[l][BUFW + ht_idx(i)] = 0xFFFFFFFF00000000ull;
    }
}

// ---------------- C[M,N] = A[M,K] @ W[N,K]^T + bias[N] ----------------
__global__ __launch_bounds__(256, 2)
void gemm_bias_nt(const float* __restrict__ A, const float* __restrict__ W,
                  const float* __restrict__ bias, float* __restrict__ C,
                  int M, int N, int K) {
    __shared__ float As[8][128];
    __shared__ float Bs[8][128];
    const int tid  = threadIdx.x;
    const int bm   = blockIdx.y * 128;
    const int bn   = blockIdx.x * 128;
    const int lrow = tid >> 1;
    const int lcol = (tid & 1) << 2;
    const int ty   = tid >> 4;
    const int tx   = tid & 15;

    float acc[8][8];
#pragma unroll
    for (int i = 0; i < 8; ++i)
#pragma unroll
        for (int j = 0; j < 8; ++j) acc[i][j] = 0.f;

    const float* Aptr = A + (size_t)(bm + lrow) * K + lcol;
    const float* Wptr = W + (size_t)(bn + lrow) * K + lcol;

    for (int k0 = 0; k0 < K; k0 += 8) {
        float4 av = *(const float4*)(Aptr + k0);
        float4 wv = *(const float4*)(Wptr + k0);
        As[lcol + 0][lrow] = av.x; As[lcol + 1][lrow] = av.y;
        As[lcol + 2][lrow] = av.z; As[lcol + 3][lrow] = av.w;
        Bs[lcol + 0][lrow] = wv.x; Bs[lcol + 1][lrow] = wv.y;
        Bs[lcol + 2][lrow] = wv.z; Bs[lcol + 3][lrow] = wv.w;
        __syncthreads();
#pragma unroll
        for (int k = 0; k < 8; ++k) {
            float4 a0 = *(const float4*)&As[k][ty * 8];
            float4 a1 = *(const float4*)&As[k][ty * 8 + 4];
            float4 b0 = *(const float4*)&Bs[k][tx * 8];
            float4 b1 = *(const float4*)&Bs[k][tx * 8 + 4];
            float ar[8] = {a0.x, a0.y, a0.z, a0.w, a1.x, a1.y, a1.z, a1.w};
            float br[8] = {b0.x, b0.y, b0.z, b0.w, b1.x, b1.y, b1.z, b1.w};
#pragma unroll
            for (int i = 0; i < 8; ++i)
#pragma unroll
                for (int j = 0; j < 8; ++j) acc[i][j] += ar[i] * br[j];
        }
        __syncthreads();
    }

#pragma unroll
    for (int i = 0; i < 8; ++i) {
        int row = bm + ty * 8 + i;
#pragma unroll
        for (int j = 0; j < 8; j += 4) {
            float4 v;
            int col = bn + tx * 8 + j;
            v.x = acc[i][j + 0] + bias[col + 0];
            v.y = acc[i][j + 1] + bias[col + 1];
            v.z = acc[i][j + 2] + bias[col + 2];
            v.w = acc[i][j + 3] + bias[col + 3];
            *(float4*)&C[(size_t)row * N + col] = v;
        }
    }
}

// ---------------- fused 3-layer wavefront MGU ----------------
// 128 CTAs x 256 threads, 1 CTA/SM. Warp w owns output j=cta*8+w of every layer.
// Wavefront step s: layer0 t=s, layer1 t=s-1, layer2 t=s-2.
// w_hh (all layers) in registers; w_ih1/2 in dynamic smem; layer-0 gi pre-GEMMed.
__global__ __launch_bounds__(RECT, 1)
void mgu_fused(const float* __restrict__ w_hh0, const float* __restrict__ w_hh1,
               const float* __restrict__ w_hh2,
               const float* __restrict__ b_hh0, const float* __restrict__ b_hh1,
               const float* __restrict__ b_hh2,
               const float* __restrict__ w_ih1, const float* __restrict__ w_ih2,
               const float* __restrict__ b_ih1, const float* __restrict__ b_ih2,
               const float* __restrict__ gi0, float* __restrict__ X2) {
    extern __shared__ float sm[];
    float* sw = sm;                      // [4][8][1024]: wih1_f, wih1_n, wih2_f, wih2_n
    float* hs = sm + 4 * 8 * 1024;       // [2][3][1024] staged h0,h1,h2

    const int cta  = blockIdx.x;
    const int tid  = threadIdx.x;
    const int warp = tid >> 5;
    const int lane = tid & 31;
    const int j    = cta * 8 + warp;

    // ---- fill smem with this CTA's w_ih rows ----
    for (int r = 0; r < 8; ++r) {
        int jr = cta * 8 + r;
        const float* s0 = w_ih1 + (size_t)jr * HID;
        const float* s1 = w_ih1 + (size_t)(HID + jr) * HID;
        const float* s2 = w_ih2 + (size_t)jr * HID;
        const float* s3 = w_ih2 + (size_t)(HID + jr) * HID;
        for (int k = tid; k < HID / 4; k += RECT) {
            ((float4*)&sw[(0 * 8 + r) * HID])[k] = ((const float4*)s0)[k];
            ((float4*)&sw[(1 * 8 + r) * HID])[k] = ((const float4*)s1)[k];
            ((float4*)&sw[(2 * 8 + r) * HID])[k] = ((const float4*)s2)[k];
            ((float4*)&sw[(3 * 8 + r) * HID])[k] = ((const float4*)s3)[k];
        }
    }

    // ---- w_hh rows (all 3 layers) into registers: 48 float4/thread ----
    float4 w0f[8], w0n[8], w1f[8], w1n[8], w2f[8], w2n[8];
#pragma unroll
    for (int i = 0; i < 8; ++i) {
        int col = 4 * (i * 32 + lane);
        w0f[i] = *(const float4*)&w_hh0[(size_t)j * HID + col];
        w0n[i] = *(const float4*)&w_hh0[(size_t)(HID + j) * HID + col];
        w1f[i] = *(const float4*)&w_hh1[(size_t)j * HID + col];
        w1n[i] = *(const float4*)&w_hh1[(size_t)(HID + j) * HID + col];
        w2f[i] = *(const float4*)&w_hh2[(size_t)j * HID + col];
        w2n[i] = *(const float4*)&w_hh2[(size_t)(HID + j) * HID + col];
    }
    const float bh0f = b_hh0[j], bh0n = b_hh0[HID + j];
    const float bi1f = b_ih1[j], bi1n = b_ih1[HID + j];
    const float bh1f = b_hh1[j], bh1n = b_hh1[HID + j];
    const float bi2f = b_ih2[j], bi2n = b_ih2[HID + j];
    const float bh2f = b_hh2[j], bh2n = b_hh2[HID + j];

    const float* r1f = sw + (0 * 8 + warp) * HID;
    const float* r1n = sw + (1 * 8 + warp) * HID;
    const float* r2f = sw + (2 * 8 + warp) * HID;
    const float* r2n = sw + (3 * 8 + warp) * HID;

    __syncthreads();

    for (int s = 0; s < T_SEQ + 2; ++s) {
        const int p = s & 1, q = p ^ 1;
        const bool act0 = s < T_SEQ;
        const bool act1 = (s >= 1) & (s <= T_SEQ);
        const bool act2 = s >= 2;

        // layer-0 gi prefetch (lane 0 = layer-0 gate lane), before the poll
        float gif0 = 0.f, gin0 = 0.f;
        if (act0 && lane == 0) {
            gif0 = __ldcg(&gi0[(size_t)s * GDIM + j]);
            gin0 = __ldcg(&gi0[(size_t)s * GDIM + HID + j]);
        }

        // ---- poll the 3 tagged vectors; stage on arrival ----
        const unsigned long long* p0 = g_ht[0] + (p ? BUFW : 0) + (size_t)tid * GRPW;
        const unsigned long long* p1 = g_ht[1] + (q ? BUFW : 0) + (size_t)tid * GRPW;
        const unsigned long long* p2 = g_ht[2] + (p ? BUFW : 0) + (size_t)tid * GRPW;
        const unsigned tg0 = (unsigned)s, tg1 = (unsigned)(s - 1), tg2 = (unsigned)(s - 2);
        bool d0 = !(s <= T_SEQ), d1 = !(s >= 1), d2 = !(s >= 2);
        while (!(d0 && d1 && d2)) {
            if (!d0) {
                unsigned a0,a1,a2,a3,b0,b1,b2,b3;
                LDV4(a0,a1,a2,a3, p0); LDV4(b0,b1,b2,b3, p0 + 2);
                if (a1 == tg0 && a3 == tg0 && b1 == tg0 && b3 == tg0) {
                    float* d = hs + (p * 3 + 0) * HID + 4 * tid;
                    d[0]=__uint_as_float(a0); d[1]=__uint_as_float(a2);
                    d[2]=__uint_as_float(b0); d[3]=__uint_as_float(b2);
                    d0 = true;
                }
            }
            if (!d1) {
                unsigned a0,a1,a2,a3,b0,b1,b2,b3;
                LDV4(a0,a1,a2,a3, p1); LDV4(b0,b1,b2,b3, p1 + 2);
                if (a1 == tg1 && a3 == tg1 && b1 == tg1 && b3 == tg1) {
                    float* d = hs + (p * 3 + 1) * HID + 4 * tid;
                    d[0]=__uint_as_float(a0); d[1]=__uint_as_float(a2);
                    d[2]=__uint_as_float(b0); d[3]=__uint_as_float(b2);
                    d1 = true;
                }
            }
            if (!d2) {
                unsigned a0,a1,a2,a3,b0,b1,b2,b3;
                LDV4(a0,a1,a2,a3, p2); LDV4(b0,b1,b2,b3, p2 + 2);
                if (a1 == tg2 && a3 == tg2 && b1 == tg2 && b3 == tg2) {
                    float* d = hs + (p * 3 + 2) * HID + 4 * tid;
                    d[0]=__uint_as_float(a0); d[1]=__uint_as_float(a2);
                    d[2]=__uint_as_float(b0); d[3]=__uint_as_float(b2);
                    d2 = true;
                }
            }
        }
        __syncthreads();

        const float* h0v = hs + (p * 3 + 0) * HID;
        const float* h1v = hs + (p * 3 + 1) * HID;
        const float* h2v = hs + (p * 3 + 2) * HID;

        // pass A: h0 -> layer0 w_hh dots (regs) + layer1 w_ih dots (smem)
        float accf0 = 0.f, accn0 = 0.f, g1f = 0.f, g1n = 0.f;
#pragma unroll
        for (int i = 0; i < 8; ++i) {
            int o = 4 * (i * 32 + lane);
            float4 h4 = *(const float4*)&h0v[o];
            float4 u  = *(const float4*)&r1f[o];
            float4 v  = *(const float4*)&r1n[o];
            accf0 += w0f[i].x*h4.x + w0f[i].y*h4.y + w0f[i].z*h4.z + w0f[i].w*h4.w;
            accn0 += w0n[i].x*h4.x + w0n[i].y*h4.y + w0n[i].z*h4.z + w0n[i].w*h4.w;
            g1f   += u.x*h4.x + u.y*h4.y + u.z*h4.z + u.w*h4.w;
            g1n   += v.x*h4.x + v.y*h4.y + v.z*h4.z + v.w*h4.w;
        }
        // pass B: h1 -> layer1 w_hh dots (regs) + layer2 w_ih dots (smem)
        float accf1 = 0.f, accn1 = 0.f, g2f = 0.f, g2n = 0.f;
#pragma unroll
        for (int i = 0; i < 8; ++i) {
            int o = 4 * (i * 32 + lane);
            float4 h4 = *(const float4*)&h1v[o];
            float4 u  = *(const float4*)&r2f[o];
            float4 v  = *(const float4*)&r2n[o];
            accf1 += w1f[i].x*h4.x + w1f[i].y*h4.y + w1f[i].z*h4.z + w1f[i].w*h4.w;
            accn1 += w1n[i].x*h4.x + w1n[i].y*h4.y + w1n[i].z*h4.z + w1n[i].w*h4.w;
            g2f   += u.x*h4.x + u.y*h4.y + u.z*h4.z + u.w*h4.w;
            g2n   += v.x*h4.x + v.y*h4.y + v.z*h4.z + v.w*h4.w;
        }
        // pass C: h2 -> layer2 w_hh dots (regs)
        float accf2 = 0.f, accn2 = 0.f;
#pragma unroll
        for (int i = 0; i < 8; ++i) {
            int o = 4 * (i * 32 + lane);
            float4 h4 = *(const float4*)&h2v[o];
            accf2 += w2f[i].x*h4.x + w2f[i].y*h4.y + w2f[i].z*h4.z + w2f[i].w*h4.w;
            accn2 += w2n[i].x*h4.x + w2n[i].y*h4.y + w2n[i].z*h4.z + w2n[i].w*h4.w;
        }

        // butterfly reduce all 10 partials (result in every lane)
#pragma unroll
        for (int o = 16; o; o >>= 1) {
            accf0 += __shfl_xor_sync(0xffffffffu, accf0, o);
            accn0 += __shfl_xor_sync(0xffffffffu, accn0, o);
            g1f   += __shfl_xor_sync(0xffffffffu, g1f,   o);
            g1n   += __shfl_xor_sync(0xffffffffu, g1n,   o);
            accf1 += __shfl_xor_sync(0xffffffffu, accf1, o);
            accn1 += __shfl_xor_sync(0xffffffffu, accn1, o);
            g2f   += __shfl_xor_sync(0xffffffffu, g2f,   o);
            g2n   += __shfl_xor_sync(0xffffffffu, g2n,   o);
            accf2 += __shfl_xor_sync(0xffffffffu, accf2, o);
            accn2 += __shfl_xor_sync(0xffffffffu, accn2, o);
        }

        // gate lanes: lane0=layer0, lane1=layer1, lane2=layer2 (reconverged math)
        float GIF = 0.f, GHF = 0.f, GIN = 0.f, GHN = 0.f, HPREV = 0.f;
        bool on = false;
        unsigned long long* pub = 0;
        unsigned ptag = 0;
        if (lane == 0) {
            GIF = gif0;        GHF = accf0 + bh0f;
            GIN = gin0;        GHN = accn0 + bh0n;
            HPREV = h0v[j];    on = act0;
            pub = g_ht[0] + (q ? BUFW : 0) + ht_idx(j);  ptag = (unsigned)(s + 1);
        } else if (lane == 1) {
            GIF = g1f + bi1f;  GHF = accf1 + bh1f;
            GIN = g1n + bi1n;  GHN = accn1 + bh1n;
            HPREV = h1v[j];    on = act1;
            pub = g_ht[1] + (p ? BUFW : 0) + ht_idx(j);  ptag = (unsigned)s;
        } else if (lane == 2) {
            GIF = g2f + bi2f;  GHF = accf2 + bh2f;
            GIN = g2n + bi2n;  GHN = accn2 + bh2n;
            HPREV = h2v[j];    on = act2;
            pub = g_ht[2] + (q ? BUFW : 0) + ht_idx(j);  ptag = (unsigned)(s - 1);
        }
        if (on) {
            float zf = GIF + GHF;
            zf = fminf(fmaxf(zf, -30.f), 30.f);
            float f = __fdividef(1.f, 1.f + __expf(-zf));
            float z = GIN + f * GHN;
            z = fminf(fmaxf(z, -15.f), 15.f);
            float e = __expf(2.f * z);
            float n = 1.f - __fdividef(2.f, e + 1.f);
            float hy = n + (1.f - f) * (HPREV - n);
            st_tagged(pub, hy, ptag);
            if (lane == 2) X2[(size_t)(s - 2) * HID + j] = hy;
        }
    }
}

// ---------------- final projection ----------------
__global__ void out_proj(const float* __restrict__ X, const float* __restrict__ w_out,
                         const float* __restrict__ b_out, float* __restrict__ out) {
    int gwarp = (blockIdx.x * blockDim.x + threadIdx.x) >> 5;
    int lane  = threadIdx.x & 31;
    if (gwarp >= T_SEQ) return;
    float acc = 0.f;
#pragma unroll
    for (int i = 0; i < HID / 32; ++i)
        acc += X[(size_t)gwarp * HID + i * 32 + lane] * w_out[i * 32 + lane];
#pragma unroll
    for (int off = 16; off; off >>= 1) acc += __shfl_down_sync(0xffffffffu, acc, off);
    if (lane == 0) out[gwarp] = acc + b_out[0];
}

// ---------------- host launcher ----------------
extern "C" void kernel_launch(void* const* d_in, const int* in_sizes, int n_in,
                              void* d_out, int out_size) {
    const float* S         = (const float*)d_in[0];
    const float* h0        = (const float*)d_in[1];
    const float* w_ih0     = (const float*)d_in[2];
    const float* w_hh0     = (const float*)d_in[3];
    const float* b_ih0     = (const float*)d_in[4];
    const float* b_hh0     = (const float*)d_in[5];
    const float* w_ih_rest = (const float*)d_in[6];
    const float* w_hh_rest = (const float*)d_in[7];
    const float* b_ih_rest = (const float*)d_in[8];
    const float* b_hh_rest = (const float*)d_in[9];
    const float* w_out     = (const float*)d_in[10];
    const float* b_out     = (const float*)d_in[11];
    float* out             = (float*)d_out;

    float *gi, *X2;
    cudaGetSymbolAddress((void**)&gi, g_gi);
    cudaGetSymbolAddress((void**)&X2, g_X2);

    const float* w_ih1 = w_ih_rest;
    const float* w_ih2 = w_ih_rest + (size_t)GDIM * HID;
    const float* b_ih1 = b_ih_rest;
    const float* b_ih2 = b_ih_rest + GDIM;
    const float* w_hh1 = w_hh_rest;
    const float* w_hh2 = w_hh_rest + (size_t)GDIM * HID;
    const float* b_hh1 = b_hh_rest;
    const float* b_hh2 = b_hh_rest + GDIM;

    const int smem_bytes = (4 * 8 * 1024 + 2 * 3 * 1024) * (int)sizeof(float); // 155648
    cudaFuncSetAttribute(mgu_fused, cudaFuncAttributeMaxDynamicSharedMemorySize,
                         smem_bytes);

    init_all<<<1, 1024>>>(h0);
    gemm_bias_nt<<<dim3(GDIM / 128, T_SEQ / 128), 256>>>(S, w_ih0, b_ih0, gi,
                                                         T_SEQ, GDIM, 128);
    mgu_fused<<<NCTA, RECT, smem_bytes>>>(w_hh0, w_hh1, w_hh2,
                                          b_hh0, b_hh1, b_hh2,
                                          w_ih1, w_ih2, b_ih1, b_ih2,
                                          gi, X2);
    out_proj<<<T_SEQ * 32 / 256, 256>>>(X2, w_out, b_out, out);
}

// round 7
// speedup vs baseline: 1.7724x; 1.1797x over previous
#include <cuda_runtime.h>
#include <math.h>

#define T_SEQ 8192
#define HID   1024
#define GDIM  2048
#define NCTA  128
#define RECT  256            // 8 warps; warp w owns output cta*8+w for all 3 layers

// tagged hidden state, slice-spread: 4 tagged 8B words per 256B granule
#define GRPW 32                         // 8B words per 256B granule
#define BUFW (256 * GRPW)               // one buffer = 64 KB

// ---------------- static scratch (no allocation) ----------------
__device__ float g_gi[T_SEQ * GDIM];    // layer-0 input projection
__device__ float g_X2[T_SEQ * HID];     // layer-2 outputs
__device__ __align__(256) unsigned long long g_ht[3][2 * BUFW];

__device__ __forceinline__ size_t ht_idx(int word) {
    return (size_t)(word >> 2) * GRPW + (word & 3);
}
__device__ __forceinline__ void st_tagged(unsigned long long* p, float v, unsigned tag) {
    unsigned long long pk = ((unsigned long long)tag << 32) |
                            (unsigned long long)__float_as_uint(v);
    asm volatile("st.global.relaxed.gpu.b64 [%0], %1;" :: "l"(p), "l"(pk) : "memory");
}
#define LDV4(d0,d1,d2,d3,ptr) \
    asm volatile("ld.volatile.global.v4.b32 {%0,%1,%2,%3}, [%4];" \
                 : "=r"(d0),"=r"(d1),"=r"(d2),"=r"(d3) : "l"(ptr))

// ---------------- init: seed all 3 layers' tagged h ----------------
__global__ void init_all(const float* __restrict__ h0) {
    int i = threadIdx.x;   // 1024 threads
#pragma unroll
    for (int l = 0; l < 3; ++l) {
        g_ht[l][ht_idx(i)] = (unsigned long long)__float_as_uint(h0[l * HID + i]);
        g_ht[l][BUFW + ht_idx(i)] = 0xFFFFFFFF00000000ull;
    }
}

// ---------------- C[M,N] = A[M,K] @ W[N,K]^T + bias[N] ----------------
__global__ __launch_bounds__(256, 2)
void gemm_bias_nt(const float* __restrict__ A, const float* __restrict__ W,
                  const float* __restrict__ bias, float* __restrict__ C,
                  int M, int N, int K) {
    __shared__ float As[8][128];
    __shared__ float Bs[8][128];
    const int tid  = threadIdx.x;
    const int bm   = blockIdx.y * 128;
    const int bn   = blockIdx.x * 128;
    const int lrow = tid >> 1;
    const int lcol = (tid & 1) << 2;
    const int ty   = tid >> 4;
    const int tx   = tid & 15;

    float acc[8][8];
#pragma unroll
    for (int i = 0; i < 8; ++i)
#pragma unroll
        for (int j = 0; j < 8; ++j) acc[i][j] = 0.f;

    const float* Aptr = A + (size_t)(bm + lrow) * K + lcol;
    const float* Wptr = W + (size_t)(bn + lrow) * K + lcol;

    for (int k0 = 0; k0 < K; k0 += 8) {
        float4 av = *(const float4*)(Aptr + k0);
        float4 wv = *(const float4*)(Wptr + k0);
        As[lcol + 0][lrow] = av.x; As[lcol + 1][lrow] = av.y;
        As[lcol + 2][lrow] = av.z; As[lcol + 3][lrow] = av.w;
        Bs[lcol + 0][lrow] = wv.x; Bs[lcol + 1][lrow] = wv.y;
        Bs[lcol + 2][lrow] = wv.z; Bs[lcol + 3][lrow] = wv.w;
        __syncthreads();
#pragma unroll
        for (int k = 0; k < 8; ++k) {
            float4 a0 = *(const float4*)&As[k][ty * 8];
            float4 a1 = *(const float4*)&As[k][ty * 8 + 4];
            float4 b0 = *(const float4*)&Bs[k][tx * 8];
            float4 b1 = *(const float4*)&Bs[k][tx * 8 + 4];
            float ar[8] = {a0.x, a0.y, a0.z, a0.w, a1.x, a1.y, a1.z, a1.w};
            float br[8] = {b0.x, b0.y, b0.z, b0.w, b1.x, b1.y, b1.z, b1.w};
#pragma unroll
            for (int i = 0; i < 8; ++i)
#pragma unroll
                for (int j = 0; j < 8; ++j) acc[i][j] += ar[i] * br[j];
        }
        __syncthreads();
    }

#pragma unroll
    for (int i = 0; i < 8; ++i) {
        int row = bm + ty * 8 + i;
#pragma unroll
        for (int j = 0; j < 8; j += 4) {
            float4 v;
            int col = bn + tx * 8 + j;
            v.x = acc[i][j + 0] + bias[col + 0];
            v.y = acc[i][j + 1] + bias[col + 1];
            v.z = acc[i][j + 2] + bias[col + 2];
            v.w = acc[i][j + 3] + bias[col + 3];
            *(float4*)&C[(size_t)row * N + col] = v;
        }
    }
}

// ---------------- fused 3-layer wavefront MGU ----------------
// 128 CTAs x 256 threads, 1 CTA/SM. Warp w owns output j=cta*8+w of every layer.
// Wavefront step s: layer0 t=s, layer1 t=s-1, layer2 t=s-2.
// w_hh0/1 in registers (128 regs); w_hh2 via L1-resident __ldg (frees 64 regs,
// avoiding the spill cliff); w_ih1/2 in dynamic smem; layer-0 gi pre-GEMMed.
__global__ __launch_bounds__(RECT, 1)
void mgu_fused(const float* __restrict__ w_hh0, const float* __restrict__ w_hh1,
               const float* __restrict__ w_hh2,
               const float* __restrict__ b_hh0, const float* __restrict__ b_hh1,
               const float* __restrict__ b_hh2,
               const float* __restrict__ w_ih1, const float* __restrict__ w_ih2,
               const float* __restrict__ b_ih1, const float* __restrict__ b_ih2,
               const float* __restrict__ gi0, float* __restrict__ X2) {
    extern __shared__ float sm[];
    float* sw = sm;                      // [4][8][1024]: wih1_f, wih1_n, wih2_f, wih2_n
    float* hs = sm + 4 * 8 * 1024;       // [2][3][1024] staged h0,h1,h2

    const int cta  = blockIdx.x;
    const int tid  = threadIdx.x;
    const int warp = tid >> 5;
    const int lane = tid & 31;
    const int j    = cta * 8 + warp;

    // ---- fill smem with this CTA's w_ih rows ----
    for (int r = 0; r < 8; ++r) {
        int jr = cta * 8 + r;
        const float* s0 = w_ih1 + (size_t)jr * HID;
        const float* s1 = w_ih1 + (size_t)(HID + jr) * HID;
        const float* s2 = w_ih2 + (size_t)jr * HID;
        const float* s3 = w_ih2 + (size_t)(HID + jr) * HID;
        for (int k = tid; k < HID / 4; k += RECT) {
            ((float4*)&sw[(0 * 8 + r) * HID])[k] = ((const float4*)s0)[k];
            ((float4*)&sw[(1 * 8 + r) * HID])[k] = ((const float4*)s1)[k];
            ((float4*)&sw[(2 * 8 + r) * HID])[k] = ((const float4*)s2)[k];
            ((float4*)&sw[(3 * 8 + r) * HID])[k] = ((const float4*)s3)[k];
        }
    }

    // ---- w_hh rows for layers 0,1 into registers: 32 float4/thread ----
    float4 w0f[8], w0n[8], w1f[8], w1n[8];
#pragma unroll
    for (int i = 0; i < 8; ++i) {
        int col = 4 * (i * 32 + lane);
        w0f[i] = *(const float4*)&w_hh0[(size_t)j * HID + col];
        w0n[i] = *(const float4*)&w_hh0[(size_t)(HID + j) * HID + col];
        w1f[i] = *(const float4*)&w_hh1[(size_t)j * HID + col];
        w1n[i] = *(const float4*)&w_hh1[(size_t)(HID + j) * HID + col];
    }
    // layer-2 w_hh rows: read through L1 each step (stays resident)
    const float4* w2f_p = (const float4*)(w_hh2 + (size_t)j * HID);
    const float4* w2n_p = (const float4*)(w_hh2 + (size_t)(HID + j) * HID);

    const float bh0f = b_hh0[j], bh0n = b_hh0[HID + j];
    const float bi1f = b_ih1[j], bi1n = b_ih1[HID + j];
    const float bh1f = b_hh1[j], bh1n = b_hh1[HID + j];
    const float bi2f = b_ih2[j], bi2n = b_ih2[HID + j];
    const float bh2f = b_hh2[j], bh2n = b_hh2[HID + j];

    const float* r1f = sw + (0 * 8 + warp) * HID;
    const float* r1n = sw + (1 * 8 + warp) * HID;
    const float* r2f = sw + (2 * 8 + warp) * HID;
    const float* r2n = sw + (3 * 8 + warp) * HID;

    // hoisted poll bases (per-thread granule) and publish slots (per-warp)
    const unsigned long long* b0p = g_ht[0] + (size_t)tid * GRPW;
    const unsigned long long* b1p = g_ht[1] + (size_t)tid * GRPW;
    const unsigned long long* b2p = g_ht[2] + (size_t)tid * GRPW;
    unsigned long long* pub0b = g_ht[0] + ht_idx(j);
    unsigned long long* pub1b = g_ht[1] + ht_idx(j);
    unsigned long long* pub2b = g_ht[2] + ht_idx(j);

    __syncthreads();

    for (int s = 0; s < T_SEQ + 2; ++s) {
        const int p = s & 1, q = p ^ 1;
        const bool act0 = s < T_SEQ;
        const bool act1 = (s >= 1) & (s <= T_SEQ);
        const bool act2 = s >= 2;

        // layer-0 gi prefetch (lane 0 = layer-0 gate lane), before the poll
        float gif0 = 0.f, gin0 = 0.f;
        if (act0 && lane == 0) {
            gif0 = __ldcg(&gi0[(size_t)s * GDIM + j]);
            gin0 = __ldcg(&gi0[(size_t)s * GDIM + HID + j]);
        }

        // ---- poll the 3 tagged vectors; stage on arrival ----
        const unsigned long long* p0 = b0p + (p ? BUFW : 0);
        const unsigned long long* p1 = b1p + (q ? BUFW : 0);
        const unsigned long long* p2 = b2p + (p ? BUFW : 0);
        const unsigned tg0 = (unsigned)s, tg1 = (unsigned)(s - 1), tg2 = (unsigned)(s - 2);
        bool d0 = !(s <= T_SEQ), d1 = !(s >= 1), d2 = !(s >= 2);
        while (!(d0 && d1 && d2)) {
            if (!d0) {
                unsigned a0,a1,a2,a3,b0,b1,b2,b3;
                LDV4(a0,a1,a2,a3, p0); LDV4(b0,b1,b2,b3, p0 + 2);
                if (a1 == tg0 && a3 == tg0 && b1 == tg0 && b3 == tg0) {
                    float* d = hs + (p * 3 + 0) * HID + 4 * tid;
                    d[0]=__uint_as_float(a0); d[1]=__uint_as_float(a2);
                    d[2]=__uint_as_float(b0); d[3]=__uint_as_float(b2);
                    d0 = true;
                }
            }
            if (!d1) {
                unsigned a0,a1,a2,a3,b0,b1,b2,b3;
                LDV4(a0,a1,a2,a3, p1); LDV4(b0,b1,b2,b3, p1 + 2);
                if (a1 == tg1 && a3 == tg1 && b1 == tg1 && b3 == tg1) {
                    float* d = hs + (p * 3 + 1) * HID + 4 * tid;
                    d[0]=__uint_as_float(a0); d[1]=__uint_as_float(a2);
                    d[2]=__uint_as_float(b0); d[3]=__uint_as_float(b2);
                    d1 = true;
                }
            }
            if (!d2) {
                unsigned a0,a1,a2,a3,b0,b1,b2,b3;
                LDV4(a0,a1,a2,a3, p2); LDV4(b0,b1,b2,b3, p2 + 2);
                if (a1 == tg2 && a3 == tg2 && b1 == tg2 && b3 == tg2) {
                    float* d = hs + (p * 3 + 2) * HID + 4 * tid;
                    d[0]=__uint_as_float(a0); d[1]=__uint_as_float(a2);
                    d[2]=__uint_as_float(b0); d[3]=__uint_as_float(b2);
                    d2 = true;
                }
            }
        }
        __syncthreads();

        const float* h0v = hs + (p * 3 + 0) * HID;
        const float* h1v = hs + (p * 3 + 1) * HID;
        const float* h2v = hs + (p * 3 + 2) * HID;

        // pass A: h0 -> layer0 w_hh dots (regs) + layer1 w_ih dots (smem)
        float accf0 = 0.f, accn0 = 0.f, g1f = 0.f, g1n = 0.f;
#pragma unroll
        for (int i = 0; i < 8; ++i) {
            int o = 4 * (i * 32 + lane);
            float4 h4 = *(const float4*)&h0v[o];
            float4 u  = *(const float4*)&r1f[o];
            float4 v  = *(const float4*)&r1n[o];
            accf0 += w0f[i].x*h4.x + w0f[i].y*h4.y + w0f[i].z*h4.z + w0f[i].w*h4.w;
            accn0 += w0n[i].x*h4.x + w0n[i].y*h4.y + w0n[i].z*h4.z + w0n[i].w*h4.w;
            g1f   += u.x*h4.x + u.y*h4.y + u.z*h4.z + u.w*h4.w;
            g1n   += v.x*h4.x + v.y*h4.y + v.z*h4.z + v.w*h4.w;
        }
        // pass B: h1 -> layer1 w_hh dots (regs) + layer2 w_ih dots (smem)
        float accf1 = 0.f, accn1 = 0.f, g2f = 0.f, g2n = 0.f;
#pragma unroll
        for (int i = 0; i < 8; ++i) {
            int o = 4 * (i * 32 + lane);
            float4 h4 = *(const float4*)&h1v[o];
            float4 u  = *(const float4*)&r2f[o];
            float4 v  = *(const float4*)&r2n[o];
            accf1 += w1f[i].x*h4.x + w1f[i].y*h4.y + w1f[i].z*h4.z + w1f[i].w*h4.w;
            accn1 += w1n[i].x*h4.x + w1n[i].y*h4.y + w1n[i].z*h4.z + w1n[i].w*h4.w;
            g2f   += u.x*h4.x + u.y*h4.y + u.z*h4.z + u.w*h4.w;
            g2n   += v.x*h4.x + v.y*h4.y + v.z*h4.z + v.w*h4.w;
        }
        // pass C: h2 -> layer2 w_hh dots, weights streamed through L1
        float accf2 = 0.f, accn2 = 0.f;
#pragma unroll
        for (int i = 0; i < 8; ++i) {
            int idx = i * 32 + lane;
            float4 h4 = *(const float4*)&h2v[4 * idx];
            float4 wa = __ldg(w2f_p + idx);
            float4 wb = __ldg(w2n_p + idx);
            accf2 += wa.x*h4.x + wa.y*h4.y + wa.z*h4.z + wa.w*h4.w;
            accn2 += wb.x*h4.x + wb.y*h4.y + wb.z*h4.z + wb.w*h4.w;
        }

        // butterfly reduce all 10 partials (result in every lane)
#pragma unroll
        for (int o = 16; o; o >>= 1) {
            accf0 += __shfl_xor_sync(0xffffffffu, accf0, o);
            accn0 += __shfl_xor_sync(0xffffffffu, accn0, o);
            g1f   += __shfl_xor_sync(0xffffffffu, g1f,   o);
            g1n   += __shfl_xor_sync(0xffffffffu, g1n,   o);
            accf1 += __shfl_xor_sync(0xffffffffu, accf1, o);
            accn1 += __shfl_xor_sync(0xffffffffu, accn1, o);
            g2f   += __shfl_xor_sync(0xffffffffu, g2f,   o);
            g2n   += __shfl_xor_sync(0xffffffffu, g2n,   o);
            accf2 += __shfl_xor_sync(0xffffffffu, accf2, o);
            accn2 += __shfl_xor_sync(0xffffffffu, accn2, o);
        }

        // gate lanes: lane0=layer0, lane1=layer1, lane2=layer2 (reconverged math)
        float GIF = 0.f, GHF = 0.f, GIN = 0.f, GHN = 0.f, HPREV = 0.f;
        bool on = false;
        unsigned long long* pub = 0;
        unsigned ptag = 0;
        if (lane == 0) {
            GIF = gif0;        GHF = accf0 + bh0f;
            GIN = gin0;        GHN = accn0 + bh0n;
            HPREV = h0v[j];    on = act0;
            pub = pub0b + (q ? BUFW : 0);  ptag = (unsigned)(s + 1);
        } else if (lane == 1) {
            GIF = g1f + bi1f;  GHF = accf1 + bh1f;
            GIN = g1n + bi1n;  GHN = accn1 + bh1n;
            HPREV = h1v[j];    on = act1;
            pub = pub1b + (p ? BUFW : 0);  ptag = (unsigned)s;
        } else if (lane == 2) {
            GIF = g2f + bi2f;  GHF = accf2 + bh2f;
            GIN = g2n + bi2n;  GHN = accn2 + bh2n;
            HPREV = h2v[j];    on = act2;
            pub = pub2b + (q ? BUFW : 0);  ptag = (unsigned)(s - 1);
        }
        if (on) {
            float zf = GIF + GHF;
            zf = fminf(fmaxf(zf, -30.f), 30.f);
            float f = __fdividef(1.f, 1.f + __expf(-zf));
            float z = GIN + f * GHN;
            z = fminf(fmaxf(z, -15.f), 15.f);
            float e = __expf(2.f * z);
            float n = 1.f - __fdividef(2.f, e + 1.f);
            float hy = n + (1.f - f) * (HPREV - n);
            st_tagged(pub, hy, ptag);
            if (lane == 2) X2[(size_t)(s - 2) * HID + j] = hy;
        }
    }
}

// ---------------- final projection ----------------
__global__ void out_proj(const float* __restrict__ X, const float* __restrict__ w_out,
                         const float* __restrict__ b_out, float* __restrict__ out) {
    int gwarp = (blockIdx.x * blockDim.x + threadIdx.x) >> 5;
    int lane  = threadIdx.x & 31;
    if (gwarp >= T_SEQ) return;
    float acc = 0.f;
#pragma unroll
    for (int i = 0; i < HID / 32; ++i)
        acc += X[(size_t)gwarp * HID + i * 32 + lane] * w_out[i * 32 + lane];
#pragma unroll
    for (int off = 16; off; off >>= 1) acc += __shfl_down_sync(0xffffffffu, acc, off);
    if (lane == 0) out[gwarp] = acc + b_out[0];
}

// ---------------- host launcher ----------------
extern "C" void kernel_launch(void* const* d_in, const int* in_sizes, int n_in,
                              void* d_out, int out_size) {
    const float* S         = (const float*)d_in[0];
    const float* h0        = (const float*)d_in[1];
    const float* w_ih0     = (const float*)d_in[2];
    const float* w_hh0     = (const float*)d_in[3];
    const float* b_ih0     = (const float*)d_in[4];
    const float* b_hh0     = (const float*)d_in[5];
    const float* w_ih_rest = (const float*)d_in[6];
    const float* w_hh_rest = (const float*)d_in[7];
    const float* b_ih_rest = (const float*)d_in[8];
    const float* b_hh_rest = (const float*)d_in[9];
    const float* w_out     = (const float*)d_in[10];
    const float* b_out     = (const float*)d_in[11];
    float* out             = (float*)d_out;

    float *gi, *X2;
    cudaGetSymbolAddress((void**)&gi, g_gi);
    cudaGetSymbolAddress((void**)&X2, g_X2);

    const float* w_ih1 = w_ih_rest;
    const float* w_ih2 = w_ih_rest + (size_t)GDIM * HID;
    const float* b_ih1 = b_ih_rest;
    const float* b_ih2 = b_ih_rest + GDIM;
    const float* w_hh1 = w_hh_rest;
    const float* w_hh2 = w_hh_rest + (size_t)GDIM * HID;
    const float* b_hh1 = b_hh_rest;
    const float* b_hh2 = b_hh_rest + GDIM;

    const int smem_bytes = (4 * 8 * 1024 + 2 * 3 * 1024) * (int)sizeof(float); // 155648
    cudaFuncSetAttribute(mgu_fused, cudaFuncAttributeMaxDynamicSharedMemorySize,
                         smem_bytes);

    init_all<<<1, 1024>>>(h0);
    gemm_bias_nt<<<dim3(GDIM / 128, T_SEQ / 128), 256>>>(S, w_ih0, b_ih0, gi,
                                                         T_SEQ, GDIM, 128);
    mgu_fused<<<NCTA, RECT, smem_bytes>>>(w_hh0, w_hh1, w_hh2,
                                          b_hh0, b_hh1, b_hh2,
                                          w_ih1, w_ih2, b_ih1, b_ih2,
                                          gi, X2);
    out_proj<<<T_SEQ * 32 / 256, 256>>>(X2, w_out, b_out, out);
}

// round 8
// speedup vs baseline: 2.0601x; 1.1623x over previous
#include <cuda_runtime.h>
#include <math.h>

#define T_SEQ 8192
#define HID   1024
#define GDIM  2048
#define NCTA  128
#define RECT  256            // 8 warps; warp w owns output cta*8+w for all 3 layers

// tagged hidden state, slice-spread: 4 tagged 8B words per 256B granule
#define GRPW 32                         // 8B words per 256B granule
#define BUFW (256 * GRPW)               // one buffer = 64 KB

// ---------------- static scratch (no allocation) ----------------
__device__ float g_gi[T_SEQ * GDIM];    // layer-0 input projection
__device__ float g_X2[T_SEQ * HID];     // layer-2 outputs
__device__ __align__(256) unsigned long long g_ht[3][2 * BUFW];

__device__ __forceinline__ size_t ht_idx(int word) {
    return (size_t)(word >> 2) * GRPW + (word & 3);
}
__device__ __forceinline__ void st_tagged(unsigned long long* p, float v, unsigned tag) {
    unsigned long long pk = ((unsigned long long)tag << 32) |
                            (unsigned long long)__float_as_uint(v);
    asm volatile("st.global.relaxed.gpu.b64 [%0], %1;" :: "l"(p), "l"(pk) : "memory");
}
#define LDV4(d0,d1,d2,d3,ptr) \
    asm volatile("ld.volatile.global.v4.b32 {%0,%1,%2,%3}, [%4];" \
                 : "=r"(d0),"=r"(d1),"=r"(d2),"=r"(d3) : "l"(ptr))

// ---------------- init: seed all 3 layers' tagged h ----------------
__global__ void init_all(const float* __restrict__ h0) {
    int i = threadIdx.x;   // 1024 threads
#pragma unroll
    for (int l = 0; l < 3; ++l) {
        g_ht[l][ht_idx(i)] = (unsigned long long)__float_as_uint(h0[l * HID + i]);
        g_ht[l][BUFW + ht_idx(i)] = 0xFFFFFFFF00000000ull;
    }
}

// ---------------- C[M,N] = A[M,K] @ W[N,K]^T + bias[N] ----------------
__global__ __launch_bounds__(256, 2)
void gemm_bias_nt(const float* __restrict__ A, const float* __restrict__ W,
                  const float* __restrict__ bias, float* __restrict__ C,
                  int M, int N, int K) {
    __shared__ float As[8][128];
    __shared__ float Bs[8][128];
    const int tid  = threadIdx.x;
    const int bm   = blockIdx.y * 128;
    const int bn   = blockIdx.x * 128;
    const int lrow = tid >> 1;
    const int lcol = (tid & 1) << 2;
    const int ty   = tid >> 4;
    const int tx   = tid & 15;

    float acc[8][8];
#pragma unroll
    for (int i = 0; i < 8; ++i)
#pragma unroll
        for (int j = 0; j < 8; ++j) acc[i][j] = 0.f;

    const float* Aptr = A + (size_t)(bm + lrow) * K + lcol;
    const float* Wptr = W + (size_t)(bn + lrow) * K + lcol;

    for (int k0 = 0; k0 < K; k0 += 8) {
        float4 av = *(const float4*)(Aptr + k0);
        float4 wv = *(const float4*)(Wptr + k0);
        As[lcol + 0][lrow] = av.x; As[lcol + 1][lrow] = av.y;
        As[lcol + 2][lrow] = av.z; As[lcol + 3][lrow] = av.w;
        Bs[lcol + 0][lrow] = wv.x; Bs[lcol + 1][lrow] = wv.y;
        Bs[lcol + 2][lrow] = wv.z; Bs[lcol + 3][lrow] = wv.w;
        __syncthreads();
#pragma unroll
        for (int k = 0; k < 8; ++k) {
            float4 a0 = *(const float4*)&As[k][ty * 8];
            float4 a1 = *(const float4*)&As[k][ty * 8 + 4];
            float4 b0 = *(const float4*)&Bs[k][tx * 8];
            float4 b1 = *(const float4*)&Bs[k][tx * 8 + 4];
            float ar[8] = {a0.x, a0.y, a0.z, a0.w, a1.x, a1.y, a1.z, a1.w};
            float br[8] = {b0.x, b0.y, b0.z, b0.w, b1.x, b1.y, b1.z, b1.w};
#pragma unroll
            for (int i = 0; i < 8; ++i)
#pragma unroll
                for (int j = 0; j < 8; ++j) acc[i][j] += ar[i] * br[j];
        }
        __syncthreads();
    }

#pragma unroll
    for (int i = 0; i < 8; ++i) {
        int row = bm + ty * 8 + i;
#pragma unroll
        for (int j = 0; j < 8; j += 4) {
            float4 v;
            int col = bn + tx * 8 + j;
            v.x = acc[i][j + 0] + bias[col + 0];
            v.y = acc[i][j + 1] + bias[col + 1];
            v.z = acc[i][j + 2] + bias[col + 2];
            v.w = acc[i][j + 3] + bias[col + 3];
            *(float4*)&C[(size_t)row * N + col] = v;
        }
    }
}

// ---------------- fused 3-layer wavefront MGU, staged pipeline ----------------
// 128 CTAs x 256 threads, 1 CTA/SM. Warp w owns output j=cta*8+w of every layer.
// Wavefront step s: layer0 t=s, layer1 t=s-1, layer2 t=s-2.
// Per step: [poll h0|passA|publish h0] [poll h1|passB|publish h1] [poll h2|passC|publish h2]
// so each layer's L2 publish->poll round trip hides under the other stages.
__global__ __launch_bounds__(RECT, 1)
void mgu_fused(const float* __restrict__ w_hh0, const float* __restrict__ w_hh1,
               const float* __restrict__ w_hh2,
               const float* __restrict__ b_hh0, const float* __restrict__ b_hh1,
               const float* __restrict__ b_hh2,
               const float* __restrict__ w_ih1, const float* __restrict__ w_ih2,
               const float* __restrict__ b_ih1, const float* __restrict__ b_ih2,
               const float* __restrict__ gi0, float* __restrict__ X2) {
    extern __shared__ float sm[];
    float* sw = sm;                      // [4][8][1024]: wih1_f, wih1_n, wih2_f, wih2_n
    float* hs = sm + 4 * 8 * 1024;       // [2][3][1024] staged h0,h1,h2

    const int cta  = blockIdx.x;
    const int tid  = threadIdx.x;
    const int warp = tid >> 5;
    const int lane = tid & 31;
    const int j    = cta * 8 + warp;

    // ---- fill smem with this CTA's w_ih rows ----
    for (int r = 0; r < 8; ++r) {
        int jr = cta * 8 + r;
        const float* s0 = w_ih1 + (size_t)jr * HID;
        const float* s1 = w_ih1 + (size_t)(HID + jr) * HID;
        const float* s2 = w_ih2 + (size_t)jr * HID;
        const float* s3 = w_ih2 + (size_t)(HID + jr) * HID;
        for (int k = tid; k < HID / 4; k += RECT) {
            ((float4*)&sw[(0 * 8 + r) * HID])[k] = ((const float4*)s0)[k];
            ((float4*)&sw[(1 * 8 + r) * HID])[k] = ((const float4*)s1)[k];
            ((float4*)&sw[(2 * 8 + r) * HID])[k] = ((const float4*)s2)[k];
            ((float4*)&sw[(3 * 8 + r) * HID])[k] = ((const float4*)s3)[k];
        }
    }

    // ---- w_hh rows for layers 0,1 into registers: 32 float4/thread ----
    float4 w0f[8], w0n[8], w1f[8], w1n[8];
#pragma unroll
    for (int i = 0; i < 8; ++i) {
        int col = 4 * (i * 32 + lane);
        w0f[i] = *(const float4*)&w_hh0[(size_t)j * HID + col];
        w0n[i] = *(const float4*)&w_hh0[(size_t)(HID + j) * HID + col];
        w1f[i] = *(const float4*)&w_hh1[(size_t)j * HID + col];
        w1n[i] = *(const float4*)&w_hh1[(size_t)(HID + j) * HID + col];
    }
    // layer-2 w_hh rows: read through L1 each step (stays resident)
    const float4* w2f_p = (const float4*)(w_hh2 + (size_t)j * HID);
    const float4* w2n_p = (const float4*)(w_hh2 + (size_t)(HID + j) * HID);

    const float bh0f = b_hh0[j], bh0n = b_hh0[HID + j];
    const float bi1f = b_ih1[j], bi1n = b_ih1[HID + j];
    const float bh1f = b_hh1[j], bh1n = b_hh1[HID + j];
    const float bi2f = b_ih2[j], bi2n = b_ih2[HID + j];
    const float bh2f = b_hh2[j], bh2n = b_hh2[HID + j];

    const float* r1f = sw + (0 * 8 + warp) * HID;
    const float* r1n = sw + (1 * 8 + warp) * HID;
    const float* r2f = sw + (2 * 8 + warp) * HID;
    const float* r2n = sw + (3 * 8 + warp) * HID;

    // hoisted poll bases (per-thread granule) and publish slots (per-warp)
    const unsigned long long* b0p = g_ht[0] + (size_t)tid * GRPW;
    const unsigned long long* b1p = g_ht[1] + (size_t)tid * GRPW;
    const unsigned long long* b2p = g_ht[2] + (size_t)tid * GRPW;
    unsigned long long* pub0b = g_ht[0] + ht_idx(j);
    unsigned long long* pub1b = g_ht[1] + ht_idx(j);
    unsigned long long* pub2b = g_ht[2] + ht_idx(j);

    __syncthreads();

    for (int s = 0; s < T_SEQ + 2; ++s) {
        const int p = s & 1, q = p ^ 1;
        const bool act0 = s < T_SEQ;
        const bool act1 = (s >= 1) & (s <= T_SEQ);
        const bool act2 = s >= 2;

        // layer-0 gi prefetch (lane 0 = layer-0 gate lane)
        float gif0 = 0.f, gin0 = 0.f;
        if (act0 && lane == 0) {
            gif0 = __ldcg(&gi0[(size_t)s * GDIM + j]);
            gin0 = __ldcg(&gi0[(size_t)s * GDIM + HID + j]);
        }

        const unsigned long long* p0 = b0p + (p ? BUFW : 0);
        const unsigned long long* p1 = b1p + (q ? BUFW : 0);
        const unsigned long long* p2 = b2p + (p ? BUFW : 0);
        const unsigned tg0 = (unsigned)s, tg1 = (unsigned)(s - 1), tg2 = (unsigned)(s - 2);
        bool d0 = !(s <= T_SEQ), d1 = !(s >= 1), d2 = !(s >= 2);
        float* st0 = hs + (p * 3 + 0) * HID + 4 * tid;
        float* st1 = hs + (p * 3 + 1) * HID + 4 * tid;
        float* st2 = hs + (p * 3 + 2) * HID + 4 * tid;

        // ======== stage 0: h0 (opportunistically drain h1/h2 polls too) ========
        while (!d0) {
            unsigned x0,x1,x2,x3, y0,y1,y2,y3;
            unsigned u0,u1,u2,u3, v0,v1,v2,v3;
            unsigned m0,m1,m2,m3, n0,n1,n2,n3;
            LDV4(x0,x1,x2,x3, p0); LDV4(y0,y1,y2,y3, p0 + 2);
            if (!d1) { LDV4(u0,u1,u2,u3, p1); LDV4(v0,v1,v2,v3, p1 + 2); }
            if (!d2) { LDV4(m0,m1,m2,m3, p2); LDV4(n0,n1,n2,n3, p2 + 2); }
            if (x1 == tg0 && x3 == tg0 && y1 == tg0 && y3 == tg0) {
                st0[0]=__uint_as_float(x0); st0[1]=__uint_as_float(x2);
                st0[2]=__uint_as_float(y0); st0[3]=__uint_as_float(y2);
                d0 = true;
            }
            if (!d1 && u1 == tg1 && u3 == tg1 && v1 == tg1 && v3 == tg1) {
                st1[0]=__uint_as_float(u0); st1[1]=__uint_as_float(u2);
                st1[2]=__uint_as_float(v0); st1[3]=__uint_as_float(v2);
                d1 = true;
            }
            if (!d2 && m1 == tg2 && m3 == tg2 && n1 == tg2 && n3 == tg2) {
                st2[0]=__uint_as_float(m0); st2[1]=__uint_as_float(m2);
                st2[2]=__uint_as_float(n0); st2[3]=__uint_as_float(n2);
                d2 = true;
            }
        }
        __syncthreads();
        const float* h0v = hs + (p * 3 + 0) * HID;

        // pass A: h0 -> layer0 w_hh dots (regs) + layer1 w_ih dots (smem)
        float accf0 = 0.f, accn0 = 0.f, g1fv = 0.f, g1nv = 0.f;
#pragma unroll
        for (int i = 0; i < 8; ++i) {
            int o = 4 * (i * 32 + lane);
            float4 h4 = *(const float4*)&h0v[o];
            float4 u  = *(const float4*)&r1f[o];
            float4 v  = *(const float4*)&r1n[o];
            accf0 += w0f[i].x*h4.x + w0f[i].y*h4.y + w0f[i].z*h4.z + w0f[i].w*h4.w;
            accn0 += w0n[i].x*h4.x + w0n[i].y*h4.y + w0n[i].z*h4.z + w0n[i].w*h4.w;
            g1fv  += u.x*h4.x + u.y*h4.y + u.z*h4.z + u.w*h4.w;
            g1nv  += v.x*h4.x + v.y*h4.y + v.z*h4.z + v.w*h4.w;
        }
#pragma unroll
        for (int o = 16; o; o >>= 1) {
            accf0 += __shfl_xor_sync(0xffffffffu, accf0, o);
            accn0 += __shfl_xor_sync(0xffffffffu, accn0, o);
            g1fv  += __shfl_xor_sync(0xffffffffu, g1fv,  o);
            g1nv  += __shfl_xor_sync(0xffffffffu, g1nv,  o);
        }
        // publish h0(s+1) immediately (early!)
        if (act0 && lane == 0) {
            float zf = gif0 + accf0 + bh0f;
            zf = fminf(fmaxf(zf, -30.f), 30.f);
            float f = __fdividef(1.f, 1.f + __expf(-zf));
            float z = gin0 + f * (accn0 + bh0n);
            z = fminf(fmaxf(z, -15.f), 15.f);
            float e = __expf(2.f * z);
            float n = 1.f - __fdividef(2.f, e + 1.f);
            float hy = n + (1.f - f) * (h0v[j] - n);
            st_tagged(pub0b + (q ? BUFW : 0), hy, (unsigned)(s + 1));
        }

        // ======== stage 1: h1 ========
        while (!d1) {
            unsigned u0,u1,u2,u3, v0,v1,v2,v3;
            unsigned m0,m1,m2,m3, n0,n1,n2,n3;
            LDV4(u0,u1,u2,u3, p1); LDV4(v0,v1,v2,v3, p1 + 2);
            if (!d2) { LDV4(m0,m1,m2,m3, p2); LDV4(n0,n1,n2,n3, p2 + 2); }
            if (u1 == tg1 && u3 == tg1 && v1 == tg1 && v3 == tg1) {
                st1[0]=__uint_as_float(u0); st1[1]=__uint_as_float(u2);
                st1[2]=__uint_as_float(v0); st1[3]=__uint_as_float(v2);
                d1 = true;
            }
            if (!d2 && m1 == tg2 && m3 == tg2 && n1 == tg2 && n3 == tg2) {
                st2[0]=__uint_as_float(m0); st2[1]=__uint_as_float(m2);
                st2[2]=__uint_as_float(n0); st2[3]=__uint_as_float(n2);
                d2 = true;
            }
        }
        __syncthreads();
        const float* h1v = hs + (p * 3 + 1) * HID;

        // pass B: h1 -> layer1 w_hh dots (regs) + layer2 w_ih dots (smem)
        float accf1 = 0.f, accn1 = 0.f, g2fv = 0.f, g2nv = 0.f;
#pragma unroll
        for (int i = 0; i < 8; ++i) {
            int o = 4 * (i * 32 + lane);
            float4 h4 = *(const float4*)&h1v[o];
            float4 u  = *(const float4*)&r2f[o];
            float4 v  = *(const float4*)&r2n[o];
            accf1 += w1f[i].x*h4.x + w1f[i].y*h4.y + w1f[i].z*h4.z + w1f[i].w*h4.w;
            accn1 += w1n[i].x*h4.x + w1n[i].y*h4.y + w1n[i].z*h4.z + w1n[i].w*h4.w;
            g2fv  += u.x*h4.x + u.y*h4.y + u.z*h4.z + u.w*h4.w;
            g2nv  += v.x*h4.x + v.y*h4.y + v.z*h4.z + v.w*h4.w;
        }
#pragma unroll
        for (int o = 16; o; o >>= 1) {
            accf1 += __shfl_xor_sync(0xffffffffu, accf1, o);
            accn1 += __shfl_xor_sync(0xffffffffu, accn1, o);
            g2fv  += __shfl_xor_sync(0xffffffffu, g2fv,  o);
            g2nv  += __shfl_xor_sync(0xffffffffu, g2nv,  o);
        }
        // publish h1(s): gate uses g1 from stage 0 (lane 1 holds reduced copy)
        if (act1 && lane == 1) {
            float zf = g1fv + bi1f + accf1 + bh1f;
            zf = fminf(fmaxf(zf, -30.f), 30.f);
            float f = __fdividef(1.f, 1.f + __expf(-zf));
            float z = g1nv + bi1n + f * (accn1 + bh1n);
            z = fminf(fmaxf(z, -15.f), 15.f);
            float e = __expf(2.f * z);
            float n = 1.f - __fdividef(2.f, e + 1.f);
            float hy = n + (1.f - f) * (h1v[j] - n);
            st_tagged(pub1b + (p ? BUFW : 0), hy, (unsigned)s);
        }

        // ======== stage 2: h2 ========
        while (!d2) {
            unsigned m0,m1,m2,m3, n0,n1,n2,n3;
            LDV4(m0,m1,m2,m3, p2); LDV4(n0,n1,n2,n3, p2 + 2);
            if (m1 == tg2 && m3 == tg2 && n1 == tg2 && n3 == tg2) {
                st2[0]=__uint_as_float(m0); st2[1]=__uint_as_float(m2);
                st2[2]=__uint_as_float(n0); st2[3]=__uint_as_float(n2);
                d2 = true;
            }
        }
        __syncthreads();
        const float* h2v = hs + (p * 3 + 2) * HID;

        // pass C: h2 -> layer2 w_hh dots, weights streamed through L1
        float accf2 = 0.f, accn2 = 0.f;
#pragma unroll
        for (int i = 0; i < 8; ++i) {
            int idx = i * 32 + lane;
            float4 h4 = *(const float4*)&h2v[4 * idx];
            float4 wa = __ldg(w2f_p + idx);
            float4 wb = __ldg(w2n_p + idx);
            accf2 += wa.x*h4.x + wa.y*h4.y + wa.z*h4.z + wa.w*h4.w;
            accn2 += wb.x*h4.x + wb.y*h4.y + wb.z*h4.z + wb.w*h4.w;
        }
#pragma unroll
        for (int o = 16; o; o >>= 1) {
            accf2 += __shfl_xor_sync(0xffffffffu, accf2, o);
            accn2 += __shfl_xor_sync(0xffffffffu, accn2, o);
        }
        // publish h2(s-1) + layer-2 output; gate uses g2 from stage 1 (lane 2)
        if (act2 && lane == 2) {
            float zf = g2fv + bi2f + accf2 + bh2f;
            zf = fminf(fmaxf(zf, -30.f), 30.f);
            float f = __fdividef(1.f, 1.f + __expf(-zf));
            float z = g2nv + bi2n + f * (accn2 + bh2n);
            z = fminf(fmaxf(z, -15.f), 15.f);
            float e = __expf(2.f * z);
            float n = 1.f - __fdividef(2.f, e + 1.f);
            float hy = n + (1.f - f) * (h2v[j] - n);
            st_tagged(pub2b + (q ? BUFW : 0), hy, (unsigned)(s - 1));
            X2[(size_t)(s - 2) * HID + j] = hy;
        }
    }
}

// ---------------- final projection ----------------
__global__ void out_proj(const float* __restrict__ X, const float* __restrict__ w_out,
                         const float* __restrict__ b_out, float* __restrict__ out) {
    int gwarp = (blockIdx.x * blockDim.x + threadIdx.x) >> 5;
    int lane  = threadIdx.x & 31;
    if (gwarp >= T_SEQ) return;
    float acc = 0.f;
#pragma unroll
    for (int i = 0; i < HID / 32; ++i)
        acc += X[(size_t)gwarp * HID + i * 32 + lane] * w_out[i * 32 + lane];
#pragma unroll
    for (int off = 16; off; off >>= 1) acc += __shfl_down_sync(0xffffffffu, acc, off);
    if (lane == 0) out[gwarp] = acc + b_out[0];
}

// ---------------- host launcher ----------------
extern "C" void kernel_launch(void* const* d_in, const int* in_sizes, int n_in,
                              void* d_out, int out_size) {
    const float* S         = (const float*)d_in[0];
    const float* h0        = (const float*)d_in[1];
    const float* w_ih0     = (const float*)d_in[2];
    const float* w_hh0     = (const float*)d_in[3];
    const float* b_ih0     = (const float*)d_in[4];
    const float* b_hh0     = (const float*)d_in[5];
    const float* w_ih_rest = (const float*)d_in[6];
    const float* w_hh_rest = (const float*)d_in[7];
    const float* b_ih_rest = (const float*)d_in[8];
    const float* b_hh_rest = (const float*)d_in[9];
    const float* w_out     = (const float*)d_in[10];
    const float* b_out     = (const float*)d_in[11];
    float* out             = (float*)d_out;

    float *gi, *X2;
    cudaGetSymbolAddress((void**)&gi, g_gi);
    cudaGetSymbolAddress((void**)&X2, g_X2);

    const float* w_ih1 = w_ih_rest;
    const float* w_ih2 = w_ih_rest + (size_t)GDIM * HID;
    const float* b_ih1 = b_ih_rest;
    const float* b_ih2 = b_ih_rest + GDIM;
    const float* w_hh1 = w_hh_rest;
    const float* w_hh2 = w_hh_rest + (size_t)GDIM * HID;
    const float* b_hh1 = b_hh_rest;
    const float* b_hh2 = b_hh_rest + GDIM;

    const int smem_bytes = (4 * 8 * 1024 + 2 * 3 * 1024) * (int)sizeof(float); // 155648
    cudaFuncSetAttribute(mgu_fused, cudaFuncAttributeMaxDynamicSharedMemorySize,
                         smem_bytes);

    init_all<<<1, 1024>>>(h0);
    gemm_bias_nt<<<dim3(GDIM / 128, T_SEQ / 128), 256>>>(S, w_ih0, b_ih0, gi,
                                                         T_SEQ, GDIM, 128);
    mgu_fused<<<NCTA, RECT, smem_bytes>>>(w_hh0, w_hh1, w_hh2,
                                          b_hh0, b_hh1, b_hh2,
                                          w_ih1, w_ih2, b_ih1, b_ih2,
                                          gi, X2);
    out_proj<<<T_SEQ * 32 / 256, 256>>>(X2, w_out, b_out, out);
}